// round 11
// baseline (speedup 1.0000x reference)
#include <cuda_runtime.h>

#define DIM    128
#define BATCH  8192
#define NITEMS 16384
#define RELS   500
#define KB     16
#define MAXSLABS 1024

typedef unsigned long long ull;

__device__ int   g_h[NITEMS], g_r[NITEMS], g_t[NITEMS];
__device__ int   g_cnt[512];            // zero at load; re-zeroed by reduce_kernel
__device__ int   g_off[RELS + 1];
__device__ int   g_cur[RELS];
__device__ int   g_bucket[NITEMS];
__device__ int   g_slab[MAXSLABS];      // packed (r << 9) | slab_index
__device__ int   g_nslabs;
__device__ __align__(16) float g_s[NITEMS];

__device__ __forceinline__ ull pack2(float a, float b) {
    ull r; asm("mov.b64 %0,{%1,%2};" : "=l"(r) : "f"(a), "f"(b)); return r;
}
__device__ __forceinline__ void ffma2(ull& d, ull a, ull b) {
    asm("fma.rn.f32x2 %0,%1,%2,%0;" : "+l"(d) : "l"(a), "l"(b));
}
__device__ __forceinline__ void unpack2(ull v, float& a, float& b) {
    asm("mov.b64 {%0,%1},%2;" : "=f"(a), "=f"(b) : "l"(v));
}
__device__ __forceinline__ void cp_async16(void* sdst, const void* gsrc) {
    unsigned s = (unsigned)__cvta_generic_to_shared(sdst);
    asm volatile("cp.async.ca.shared.global [%0], [%1], 16;" :: "r"(s), "l"(gsrc));
}
__device__ __forceinline__ void cp_commit() { asm volatile("cp.async.commit_group;"); }
__device__ __forceinline__ void cp_wait0()  { asm volatile("cp.async.wait_group 0;" ::: "memory"); }

// Extract h/r/t columns + relation histogram. Dtype detected inline:
// int64 triples (indices < 500) have all-zero odd 32-bit words.
__global__ void prep_kernel(const int* __restrict__ pos, const int* __restrict__ neg) {
    int i = blockIdx.x * blockDim.x + threadIdx.x;
    if (i >= NITEMS) return;
    const int sh = ((pos[1] | pos[3] | pos[5] | pos[7] |
                     pos[9] | pos[11] | pos[13] | pos[15]) == 0) ? 1 : 0;
    const int* q = (i < BATCH) ? pos : neg;
    const int  j = (i < BATCH) ? i : i - BATCH;
    int rr = q[(3 * j + 1) << sh];
    g_h[i] = q[(3 * j + 0) << sh];
    g_r[i] = rr;
    g_t[i] = q[(3 * j + 2) << sh];
    atomicAdd(&g_cnt[rr], 1);
}

// Prefix-scan counts -> offsets; also build the slab worklist.
__global__ void scan_kernel() {      // 512 threads
    __shared__ int ws[16], ws2[16];
    const int tid = threadIdx.x, lane = tid & 31, w = tid >> 5;
    const int x  = (tid < RELS) ? g_cnt[tid] : 0;          // items for relation tid
    const int y  = (2 * x + 63) >> 6;                       // slabs for relation tid

    int v = x, u = y;
    #pragma unroll
    for (int o = 1; o < 32; o <<= 1) {
        int a = __shfl_up_sync(0xffffffffu, v, o);
        int b = __shfl_up_sync(0xffffffffu, u, o);
        if (lane >= o) { v += a; u += b; }
    }
    if (lane == 31) { ws[w] = v; ws2[w] = u; }
    __syncthreads();
    if (w == 0) {
        int s  = (lane < 16) ? ws[lane]  : 0;
        int s2 = (lane < 16) ? ws2[lane] : 0;
        #pragma unroll
        for (int o = 1; o < 16; o <<= 1) {
            int a = __shfl_up_sync(0xffffffffu, s,  o);
            int b = __shfl_up_sync(0xffffffffu, s2, o);
            if (lane >= o) { s += a; s2 += b; }
        }
        if (lane < 16) { ws[lane] = s; ws2[lane] = s2; }
    }
    __syncthreads();
    const int inc  = v + ((w > 0) ? ws[w - 1]  : 0);
    const int incs = u + ((w > 0) ? ws2[w - 1] : 0);
    if (tid < RELS) {
        g_off[tid + 1] = inc;
        g_cur[tid]     = inc - x;
        int sb = incs - y;
        for (int s = 0; s < y; s++)
            g_slab[sb + s] = (tid << 9) | s;
    }
    if (tid == 0)   g_off[0] = 0;
    if (tid == 511) g_nslabs = incs;
}

__global__ void scatter_kernel() {
    int i = blockIdx.x * blockDim.x + threadIdx.x;
    if (i >= NITEMS) return;
    int p = atomicAdd(&g_cur[g_r[i]], 1);
    g_bucket[p] = i;
}

// R6/R8 mainloop (measured 57% fma): float4 V + pack MOVs, LDS.64 M operands.
// MASKED=false is the dense path; masked variant only for tail slabs.
template<bool MASKED>
__device__ __forceinline__ void mainloop(
    const float* __restrict__ Mr, const float* __restrict__ ent,
    const int* s_eid,
    float (*Mt)[KB][DIM], float (*Vp)[KB][68],
    ull acc[8][4], int tid, int tx, int ty, bool active)
{
    float4 vr[2];

    // ---- prologue: stage panel 0 into buffer 0 ----
    {
        #pragma unroll
        for (int j = 0; j < 4; j++) {
            int idx = tid + 128 * j, row = idx >> 5, c4 = idx & 31;
            cp_async16(&Mt[0][row][c4 * 4], &Mr[row * DIM + c4 * 4]);
        }
        cp_commit();
        #pragma unroll
        for (int j = 0; j < 2; j++) {
            int idx = tid + 128 * j, v = idx >> 2, q = idx & 3;
            vr[j] = *(const float4*)&ent[(long long)s_eid[v] * DIM + q * 4];
        }
        cp_wait0();
        #pragma unroll
        for (int j = 0; j < 2; j++) {
            int idx = tid + 128 * j, v = idx >> 2, q = idx & 3;
            Vp[0][q * 4 + 0][v] = vr[j].x;
            Vp[0][q * 4 + 1][v] = vr[j].y;
            Vp[0][q * 4 + 2][v] = vr[j].z;
            Vp[0][q * 4 + 3][v] = vr[j].w;
        }
        __syncthreads();
    }

    #pragma unroll 1
    for (int kbi = 0; kbi < 8; kbi++) {
        const int cur = kbi & 1, nxt = cur ^ 1;
        const int kb2 = (kbi + 1) * KB;

        // issue next panel's loads before computing current
        if (kbi < 7) {
            #pragma unroll
            for (int j = 0; j < 4; j++) {
                int idx = tid + 128 * j, row = idx >> 5, c4 = idx & 31;
                cp_async16(&Mt[nxt][row][c4 * 4], &Mr[(kb2 + row) * DIM + c4 * 4]);
            }
            cp_commit();
            #pragma unroll
            for (int j = 0; j < 2; j++) {
                int idx = tid + 128 * j, v = idx >> 2, q = idx & 3;
                vr[j] = *(const float4*)&ent[(long long)s_eid[v] * DIM + kb2 + q * 4];
            }
        }

        // ---- compute on current buffer ----
        if (!MASKED || active) {
            #pragma unroll
            for (int k = 0; k < KB; k++) {
                const ull* mrow = (const ull*)&Mt[cur][k][0];
                const ull mp0 = mrow[2 * tx];
                const ull mp1 = mrow[2 * tx + 1];
                const ull mp2 = mrow[32 + 2 * tx];
                const ull mp3 = mrow[32 + 2 * tx + 1];
                const float4 va = *(const float4*)&Vp[cur][k][8 * ty];
                const float4 vb = *(const float4*)&Vp[cur][k][8 * ty + 4];
                const float vs[8] = {va.x, va.y, va.z, va.w, vb.x, vb.y, vb.z, vb.w};
                #pragma unroll
                for (int i = 0; i < 8; i++) {
                    ull vv = pack2(vs[i], vs[i]);
                    ffma2(acc[i][0], mp0, vv);
                    ffma2(acc[i][1], mp1, vv);
                    ffma2(acc[i][2], mp2, vv);
                    ffma2(acc[i][3], mp3, vv);
                }
            }
        }

        if (kbi < 7) {
            cp_wait0();
            #pragma unroll
            for (int j = 0; j < 2; j++) {
                int idx = tid + 128 * j, v = idx >> 2, q = idx & 3;
                Vp[nxt][q * 4 + 0][v] = vr[j].x;
                Vp[nxt][q * 4 + 1][v] = vr[j].y;
                Vp[nxt][q * 4 + 2][v] = vr[j].z;
                Vp[nxt][q * 4 + 3][v] = vr[j].w;
            }
        }
        __syncthreads();
    }
}

__global__ void __launch_bounds__(128, 4) score_kernel(
    const float* __restrict__ ent,
    const float* __restrict__ rel,
    const float* __restrict__ tm)
{
    const int b = blockIdx.x;
    if (b >= g_nslabs) return;
    const int packed = g_slab[b];
    const int r    = packed >> 9;
    const int slab = (packed & 511) << 6;    // first vector index of this slab

    const int tid = threadIdx.x;
    const int tx  = tid & 15;      // col group (8 cols: 4tx.. and 64+4tx..)
    const int ty  = tid >> 4;      // vec group (vectors 8ty..8ty+7)
    const int w   = tid >> 5;      // warp: owns vectors 16w..16w+15 of the slab

    __shared__ __align__(16) float Mt[2][KB][DIM];   // double-buffered M k-panels
    __shared__ __align__(16) float Vp[2][KB][68];    // double-buffered V k-panels
    __shared__ float rnorm[DIM];
    __shared__ float sbuf[4];
    __shared__ int   s_eid[64];

    const int beg = g_off[r];
    const int n   = g_off[r + 1] - beg;
    const int nv  = 2 * n;
    const int m_slab = min(64, nv - slab);           // live vectors in this slab
    const bool active = (16 * w < m_slab);           // uniform per warp
    const float* Mr = tm + (long long)r * (DIM * DIM);

    // Normalized relation vector
    {
        float v = rel[r * DIM + tid];
        float ss = v * v;
        #pragma unroll
        for (int o = 16; o > 0; o >>= 1) ss += __shfl_xor_sync(0xffffffffu, ss, o);
        if ((tid & 31) == 0) sbuf[tid >> 5] = ss;
        __syncthreads();
        float tot = sbuf[0] + sbuf[1] + sbuf[2] + sbuf[3];
        rnorm[tid] = v / fmaxf(sqrtf(tot), 1e-12f);
    }

    // Gather entity ids for this slab's 64 vectors (h,t interleaved)
    if (tid < 64) {
        int vec = slab + tid;
        int e = 0;
        if (vec < nv) {
            int id = g_bucket[beg + (vec >> 1)];
            e = (vec & 1) ? g_t[id] : g_h[id];
        }
        s_eid[tid] = e;
    }
    __syncthreads();

    float4 ra = *(const float4*)&rnorm[4 * tx];
    float4 rb = *(const float4*)&rnorm[64 + 4 * tx];

    ull acc[8][4];
    #pragma unroll
    for (int i = 0; i < 8; i++)
        #pragma unroll
        for (int j = 0; j < 4; j++) acc[i][j] = 0ull;

    if (m_slab == 64)
        mainloop<false>(Mr, ent, s_eid, Mt, Vp, acc, tid, tx, ty, true);
    else
        mainloop<true>(Mr, ent, s_eid, Mt, Vp, acc, tid, tx, ty, active);

    if (!active) return;

    // ---- barrier-free epilogue: 16-lane (half-warp) shuffle reductions ----
    float invv[8];
    #pragma unroll
    for (int i = 0; i < 8; i++) {
        float a, b2, c, d, e, f, g, h;
        unpack2(acc[i][0], a, b2);
        unpack2(acc[i][1], c, d);
        unpack2(acc[i][2], e, f);
        unpack2(acc[i][3], g, h);
        float ss = a * a + b2 * b2 + c * c + d * d + e * e + f * f + g * g + h * h;
        #pragma unroll
        for (int o = 1; o < 16; o <<= 1)
            ss += __shfl_xor_sync(0xffffffffu, ss, o);
        invv[i] = 1.0f / fmaxf(sqrtf(ss), 1e-12f);
    }

    #pragma unroll
    for (int p = 0; p < 4; p++) {
        float h0, h1, h2, h3, h4, h5, h6, h7;
        float t0, t1, t2, t3, t4, t5, t6, t7;
        unpack2(acc[2 * p][0], h0, h1);
        unpack2(acc[2 * p][1], h2, h3);
        unpack2(acc[2 * p][2], h4, h5);
        unpack2(acc[2 * p][3], h6, h7);
        unpack2(acc[2 * p + 1][0], t0, t1);
        unpack2(acc[2 * p + 1][1], t2, t3);
        unpack2(acc[2 * p + 1][2], t4, t5);
        unpack2(acc[2 * p + 1][3], t6, t7);
        const float ih = invv[2 * p];
        const float it = invv[2 * p + 1];
        float sc = fabsf(h0 * ih + ra.x - t0 * it)
                 + fabsf(h1 * ih + ra.y - t1 * it)
                 + fabsf(h2 * ih + ra.z - t2 * it)
                 + fabsf(h3 * ih + ra.w - t3 * it)
                 + fabsf(h4 * ih + rb.x - t4 * it)
                 + fabsf(h5 * ih + rb.y - t5 * it)
                 + fabsf(h6 * ih + rb.z - t6 * it)
                 + fabsf(h7 * ih + rb.w - t7 * it);
        #pragma unroll
        for (int o = 1; o < 16; o <<= 1)
            sc += __shfl_xor_sync(0xffffffffu, sc, o);
        if (tx == 0) {
            int item_local = (slab >> 1) + 4 * ty + p;
            if (item_local < n)
                g_s[g_bucket[beg + item_local]] = sc;
        }
    }
}

__global__ void reduce_kernel(float* __restrict__ out) {   // 1024 threads
    __shared__ float sbuf[32];
    const int tid = threadIdx.x;
    float v = 0.f;
    #pragma unroll
    for (int it = 0; it < 2; it++) {
        int i = tid + 1024 * it;
        float4 p = *(const float4*)&g_s[4 * i];
        float4 q = *(const float4*)&g_s[4 * i + BATCH];
        v += fmaxf(p.x - q.x + 1.0f, 0.0f);
        v += fmaxf(p.y - q.y + 1.0f, 0.0f);
        v += fmaxf(p.z - q.z + 1.0f, 0.0f);
        v += fmaxf(p.w - q.w + 1.0f, 0.0f);
    }
    #pragma unroll
    for (int o = 16; o > 0; o >>= 1)
        v += __shfl_xor_sync(0xffffffffu, v, o);
    if ((tid & 31) == 0) sbuf[tid >> 5] = v;
    // re-zero histogram for the next graph replay (invariant: zero on entry)
    if (tid < 512) g_cnt[tid] = 0;
    __syncthreads();
    if (tid == 0) {
        float s = 0.f;
        #pragma unroll
        for (int i = 0; i < 32; i++) s += sbuf[i];
        out[0] = s * (1.0f / (float)BATCH);
    }
}

extern "C" void kernel_launch(void* const* d_in, const int* in_sizes, int n_in,
                              void* d_out, int out_size) {
    const void*  pos = d_in[0];
    const void*  neg = d_in[1];
    const float* ent = (const float*)d_in[2];
    const float* rel = (const float*)d_in[3];
    const float* tm  = (const float*)d_in[4];

    prep_kernel<<<(NITEMS + 255) / 256, 256>>>((const int*)pos, (const int*)neg);
    scan_kernel<<<1, 512>>>();
    scatter_kernel<<<(NITEMS + 255) / 256, 256>>>();
    score_kernel<<<MAXSLABS, 128>>>(ent, rel, tm);
    reduce_kernel<<<1, 1024>>>((float*)d_out);
}

// round 12
// speedup vs baseline: 1.0054x; 1.0054x over previous
#include <cuda_runtime.h>

#define DIM    128
#define BATCH  8192
#define NITEMS 16384
#define RELS   500
#define KB     16
#define MAXSLABS 1024

typedef unsigned long long ull;

__device__ int   g_h[NITEMS], g_r[NITEMS], g_t[NITEMS];
__device__ int   g_cnt[512];            // zero at load; re-zeroed by reduce_kernel
__device__ int   g_off[RELS + 1];
__device__ int   g_cur[RELS];
__device__ int   g_bucket[NITEMS];
__device__ int   g_slab[MAXSLABS];      // packed (r << 9) | slab_index
__device__ int   g_nslabs;
__device__ __align__(16) float g_s[NITEMS];

__device__ __forceinline__ ull pack2(float a, float b) {
    ull r; asm("mov.b64 %0,{%1,%2};" : "=l"(r) : "f"(a), "f"(b)); return r;
}
__device__ __forceinline__ void ffma2(ull& d, ull a, ull b) {
    asm("fma.rn.f32x2 %0,%1,%2,%0;" : "+l"(d) : "l"(a), "l"(b));
}
__device__ __forceinline__ void unpack2(ull v, float& a, float& b) {
    asm("mov.b64 {%0,%1},%2;" : "=f"(a), "=f"(b) : "l"(v));
}
__device__ __forceinline__ void cp_async16(void* sdst, const void* gsrc) {
    unsigned s = (unsigned)__cvta_generic_to_shared(sdst);
    asm volatile("cp.async.ca.shared.global [%0], [%1], 16;" :: "r"(s), "l"(gsrc));
}
__device__ __forceinline__ void cp_commit() { asm volatile("cp.async.commit_group;"); }
__device__ __forceinline__ void cp_wait0()  { asm volatile("cp.async.wait_group 0;" ::: "memory"); }

// Extract h/r/t columns + relation histogram. Dtype detected inline:
// int64 triples (indices < 500) have all-zero odd 32-bit words.
__global__ void prep_kernel(const int* __restrict__ pos, const int* __restrict__ neg) {
    int i = blockIdx.x * blockDim.x + threadIdx.x;
    if (i >= NITEMS) return;
    const int sh = ((pos[1] | pos[3] | pos[5] | pos[7] |
                     pos[9] | pos[11] | pos[13] | pos[15]) == 0) ? 1 : 0;
    const int* q = (i < BATCH) ? pos : neg;
    const int  j = (i < BATCH) ? i : i - BATCH;
    int rr = q[(3 * j + 1) << sh];
    g_h[i] = q[(3 * j + 0) << sh];
    g_r[i] = rr;
    g_t[i] = q[(3 * j + 2) << sh];
    atomicAdd(&g_cnt[rr], 1);
}

// Prefix-scan counts -> offsets; also build the slab worklist.
__global__ void scan_kernel() {      // 512 threads
    __shared__ int ws[16], ws2[16];
    const int tid = threadIdx.x, lane = tid & 31, w = tid >> 5;
    const int x  = (tid < RELS) ? g_cnt[tid] : 0;          // items for relation tid
    const int y  = (2 * x + 63) >> 6;                       // slabs for relation tid

    int v = x, u = y;
    #pragma unroll
    for (int o = 1; o < 32; o <<= 1) {
        int a = __shfl_up_sync(0xffffffffu, v, o);
        int b = __shfl_up_sync(0xffffffffu, u, o);
        if (lane >= o) { v += a; u += b; }
    }
    if (lane == 31) { ws[w] = v; ws2[w] = u; }
    __syncthreads();
    if (w == 0) {
        int s  = (lane < 16) ? ws[lane]  : 0;
        int s2 = (lane < 16) ? ws2[lane] : 0;
        #pragma unroll
        for (int o = 1; o < 16; o <<= 1) {
            int a = __shfl_up_sync(0xffffffffu, s,  o);
            int b = __shfl_up_sync(0xffffffffu, s2, o);
            if (lane >= o) { s += a; s2 += b; }
        }
        if (lane < 16) { ws[lane] = s; ws2[lane] = s2; }
    }
    __syncthreads();
    const int inc  = v + ((w > 0) ? ws[w - 1]  : 0);
    const int incs = u + ((w > 0) ? ws2[w - 1] : 0);
    if (tid < RELS) {
        g_off[tid + 1] = inc;
        g_cur[tid]     = inc - x;
        int sb = incs - y;
        for (int s = 0; s < y; s++)
            g_slab[sb + s] = (tid << 9) | s;
    }
    if (tid == 0)   g_off[0] = 0;
    if (tid == 511) g_nslabs = incs;
}

__global__ void scatter_kernel() {
    int i = blockIdx.x * blockDim.x + threadIdx.x;
    if (i >= NITEMS) return;
    int p = atomicAdd(&g_cur[g_r[i]], 1);
    g_bucket[p] = i;
}

// R6/R8 mainloop (measured 57% fma): float4 V + pack MOVs, LDS.64 M operands.
// MASKED=false is the dense path; masked variant only for tail slabs.
template<bool MASKED>
__device__ __forceinline__ void mainloop(
    const float* __restrict__ Mr, const float* __restrict__ ent,
    const int* s_eid,
    float (*Mt)[KB][DIM], float (*Vp)[KB][68],
    ull acc[8][4], int tid, int tx, int ty, bool active)
{
    float4 vr[2];

    // ---- prologue: stage panel 0 into buffer 0 ----
    {
        #pragma unroll
        for (int j = 0; j < 4; j++) {
            int idx = tid + 128 * j, row = idx >> 5, c4 = idx & 31;
            cp_async16(&Mt[0][row][c4 * 4], &Mr[row * DIM + c4 * 4]);
        }
        cp_commit();
        #pragma unroll
        for (int j = 0; j < 2; j++) {
            int idx = tid + 128 * j, v = idx >> 2, q = idx & 3;
            vr[j] = *(const float4*)&ent[(long long)s_eid[v] * DIM + q * 4];
        }
        cp_wait0();
        #pragma unroll
        for (int j = 0; j < 2; j++) {
            int idx = tid + 128 * j, v = idx >> 2, q = idx & 3;
            Vp[0][q * 4 + 0][v] = vr[j].x;
            Vp[0][q * 4 + 1][v] = vr[j].y;
            Vp[0][q * 4 + 2][v] = vr[j].z;
            Vp[0][q * 4 + 3][v] = vr[j].w;
        }
        __syncthreads();
    }

    #pragma unroll 1
    for (int kbi = 0; kbi < 8; kbi++) {
        const int cur = kbi & 1, nxt = cur ^ 1;
        const int kb2 = (kbi + 1) * KB;

        // issue next panel's loads before computing current
        if (kbi < 7) {
            #pragma unroll
            for (int j = 0; j < 4; j++) {
                int idx = tid + 128 * j, row = idx >> 5, c4 = idx & 31;
                cp_async16(&Mt[nxt][row][c4 * 4], &Mr[(kb2 + row) * DIM + c4 * 4]);
            }
            cp_commit();
            #pragma unroll
            for (int j = 0; j < 2; j++) {
                int idx = tid + 128 * j, v = idx >> 2, q = idx & 3;
                vr[j] = *(const float4*)&ent[(long long)s_eid[v] * DIM + kb2 + q * 4];
            }
        }

        // ---- compute on current buffer ----
        if (!MASKED || active) {
            #pragma unroll
            for (int k = 0; k < KB; k++) {
                const ull* mrow = (const ull*)&Mt[cur][k][0];
                const ull mp0 = mrow[2 * tx];
                const ull mp1 = mrow[2 * tx + 1];
                const ull mp2 = mrow[32 + 2 * tx];
                const ull mp3 = mrow[32 + 2 * tx + 1];
                const float4 va = *(const float4*)&Vp[cur][k][8 * ty];
                const float4 vb = *(const float4*)&Vp[cur][k][8 * ty + 4];
                const float vs[8] = {va.x, va.y, va.z, va.w, vb.x, vb.y, vb.z, vb.w};
                #pragma unroll
                for (int i = 0; i < 8; i++) {
                    ull vv = pack2(vs[i], vs[i]);
                    ffma2(acc[i][0], mp0, vv);
                    ffma2(acc[i][1], mp1, vv);
                    ffma2(acc[i][2], mp2, vv);
                    ffma2(acc[i][3], mp3, vv);
                }
            }
        }

        if (kbi < 7) {
            cp_wait0();
            #pragma unroll
            for (int j = 0; j < 2; j++) {
                int idx = tid + 128 * j, v = idx >> 2, q = idx & 3;
                Vp[nxt][q * 4 + 0][v] = vr[j].x;
                Vp[nxt][q * 4 + 1][v] = vr[j].y;
                Vp[nxt][q * 4 + 2][v] = vr[j].z;
                Vp[nxt][q * 4 + 3][v] = vr[j].w;
            }
        }
        __syncthreads();
    }
}

__global__ void __launch_bounds__(128, 4) score_kernel(
    const float* __restrict__ ent,
    const float* __restrict__ rel,
    const float* __restrict__ tm)
{
    const int b = blockIdx.x;
    if (b >= g_nslabs) return;
    const int packed = g_slab[b];
    const int r    = packed >> 9;
    const int slab = (packed & 511) << 6;    // first vector index of this slab

    const int tid = threadIdx.x;
    const int tx  = tid & 15;      // col group (8 cols: 4tx.. and 64+4tx..)
    const int ty  = tid >> 4;      // vec group (vectors 8ty..8ty+7)
    const int w   = tid >> 5;      // warp: owns vectors 16w..16w+15 of the slab

    __shared__ __align__(16) float Mt[2][KB][DIM];   // double-buffered M k-panels
    __shared__ __align__(16) float Vp[2][KB][68];    // double-buffered V k-panels
    __shared__ float rnorm[DIM];
    __shared__ float sbuf[4];
    __shared__ int   s_eid[64];

    const int beg = g_off[r];
    const int n   = g_off[r + 1] - beg;
    const int nv  = 2 * n;
    const int m_slab = min(64, nv - slab);           // live vectors in this slab
    const bool active = (16 * w < m_slab);           // uniform per warp
    const float* Mr = tm + (long long)r * (DIM * DIM);

    // Normalized relation vector
    {
        float v = rel[r * DIM + tid];
        float ss = v * v;
        #pragma unroll
        for (int o = 16; o > 0; o >>= 1) ss += __shfl_xor_sync(0xffffffffu, ss, o);
        if ((tid & 31) == 0) sbuf[tid >> 5] = ss;
        __syncthreads();
        float tot = sbuf[0] + sbuf[1] + sbuf[2] + sbuf[3];
        rnorm[tid] = v / fmaxf(sqrtf(tot), 1e-12f);
    }

    // Gather entity ids for this slab's 64 vectors (h,t interleaved)
    if (tid < 64) {
        int vec = slab + tid;
        int e = 0;
        if (vec < nv) {
            int id = g_bucket[beg + (vec >> 1)];
            e = (vec & 1) ? g_t[id] : g_h[id];
        }
        s_eid[tid] = e;
    }
    __syncthreads();

    float4 ra = *(const float4*)&rnorm[4 * tx];
    float4 rb = *(const float4*)&rnorm[64 + 4 * tx];

    ull acc[8][4];
    #pragma unroll
    for (int i = 0; i < 8; i++)
        #pragma unroll
        for (int j = 0; j < 4; j++) acc[i][j] = 0ull;

    if (m_slab == 64)
        mainloop<false>(Mr, ent, s_eid, Mt, Vp, acc, tid, tx, ty, true);
    else
        mainloop<true>(Mr, ent, s_eid, Mt, Vp, acc, tid, tx, ty, active);

    if (!active) return;

    // ---- barrier-free epilogue: 16-lane (half-warp) shuffle reductions ----
    float invv[8];
    #pragma unroll
    for (int i = 0; i < 8; i++) {
        float a, b2, c, d, e, f, g, h;
        unpack2(acc[i][0], a, b2);
        unpack2(acc[i][1], c, d);
        unpack2(acc[i][2], e, f);
        unpack2(acc[i][3], g, h);
        float ss = a * a + b2 * b2 + c * c + d * d + e * e + f * f + g * g + h * h;
        #pragma unroll
        for (int o = 1; o < 16; o <<= 1)
            ss += __shfl_xor_sync(0xffffffffu, ss, o);
        invv[i] = 1.0f / fmaxf(sqrtf(ss), 1e-12f);
    }

    #pragma unroll
    for (int p = 0; p < 4; p++) {
        float h0, h1, h2, h3, h4, h5, h6, h7;
        float t0, t1, t2, t3, t4, t5, t6, t7;
        unpack2(acc[2 * p][0], h0, h1);
        unpack2(acc[2 * p][1], h2, h3);
        unpack2(acc[2 * p][2], h4, h5);
        unpack2(acc[2 * p][3], h6, h7);
        unpack2(acc[2 * p + 1][0], t0, t1);
        unpack2(acc[2 * p + 1][1], t2, t3);
        unpack2(acc[2 * p + 1][2], t4, t5);
        unpack2(acc[2 * p + 1][3], t6, t7);
        const float ih = invv[2 * p];
        const float it = invv[2 * p + 1];
        float sc = fabsf(h0 * ih + ra.x - t0 * it)
                 + fabsf(h1 * ih + ra.y - t1 * it)
                 + fabsf(h2 * ih + ra.z - t2 * it)
                 + fabsf(h3 * ih + ra.w - t3 * it)
                 + fabsf(h4 * ih + rb.x - t4 * it)
                 + fabsf(h5 * ih + rb.y - t5 * it)
                 + fabsf(h6 * ih + rb.z - t6 * it)
                 + fabsf(h7 * ih + rb.w - t7 * it);
        #pragma unroll
        for (int o = 1; o < 16; o <<= 1)
            sc += __shfl_xor_sync(0xffffffffu, sc, o);
        if (tx == 0) {
            int item_local = (slab >> 1) + 4 * ty + p;
            if (item_local < n)
                g_s[g_bucket[beg + item_local]] = sc;
        }
    }
}

__global__ void reduce_kernel(float* __restrict__ out) {   // 1024 threads
    __shared__ float sbuf[32];
    const int tid = threadIdx.x;
    float v = 0.f;
    #pragma unroll
    for (int it = 0; it < 2; it++) {
        int i = tid + 1024 * it;
        float4 p = *(const float4*)&g_s[4 * i];
        float4 q = *(const float4*)&g_s[4 * i + BATCH];
        v += fmaxf(p.x - q.x + 1.0f, 0.0f);
        v += fmaxf(p.y - q.y + 1.0f, 0.0f);
        v += fmaxf(p.z - q.z + 1.0f, 0.0f);
        v += fmaxf(p.w - q.w + 1.0f, 0.0f);
    }
    #pragma unroll
    for (int o = 16; o > 0; o >>= 1)
        v += __shfl_xor_sync(0xffffffffu, v, o);
    if ((tid & 31) == 0) sbuf[tid >> 5] = v;
    // re-zero histogram for the next graph replay (invariant: zero on entry)
    if (tid < 512) g_cnt[tid] = 0;
    __syncthreads();
    if (tid == 0) {
        float s = 0.f;
        #pragma unroll
        for (int i = 0; i < 32; i++) s += sbuf[i];
        out[0] = s * (1.0f / (float)BATCH);
    }
}

extern "C" void kernel_launch(void* const* d_in, const int* in_sizes, int n_in,
                              void* d_out, int out_size) {
    const void*  pos = d_in[0];
    const void*  neg = d_in[1];
    const float* ent = (const float*)d_in[2];
    const float* rel = (const float*)d_in[3];
    const float* tm  = (const float*)d_in[4];

    prep_kernel<<<(NITEMS + 255) / 256, 256>>>((const int*)pos, (const int*)neg);
    scan_kernel<<<1, 512>>>();
    scatter_kernel<<<(NITEMS + 255) / 256, 256>>>();
    score_kernel<<<MAXSLABS, 128>>>(ent, rel, tm);
    reduce_kernel<<<1, 1024>>>((float*)d_out);
}

// round 13
// speedup vs baseline: 1.0061x; 1.0007x over previous
#include <cuda_runtime.h>

#define DIM    128
#define BATCH  8192
#define NITEMS 16384
#define RELS   500
#define KB     16
#define MAXSLABS 1024

typedef unsigned long long ull;

__device__ int   g_h[NITEMS], g_r[NITEMS], g_t[NITEMS];
__device__ int   g_cnt[512];            // zero at load; re-zeroed by reduce_kernel
__device__ int   g_off[RELS + 1];
__device__ int   g_cur[RELS];
__device__ int   g_bucket[NITEMS];
__device__ int   g_slab[MAXSLABS];      // packed (r << 9) | slab_index
__device__ int   g_nslabs;
__device__ __align__(16) float g_s[NITEMS];

__device__ __forceinline__ ull pack2(float a, float b) {
    ull r; asm("mov.b64 %0,{%1,%2};" : "=l"(r) : "f"(a), "f"(b)); return r;
}
__device__ __forceinline__ void ffma2(ull& d, ull a, ull b) {
    asm("fma.rn.f32x2 %0,%1,%2,%0;" : "+l"(d) : "l"(a), "l"(b));
}
__device__ __forceinline__ void unpack2(ull v, float& a, float& b) {
    asm("mov.b64 {%0,%1},%2;" : "=f"(a), "=f"(b) : "l"(v));
}
__device__ __forceinline__ void cp_async16(void* sdst, const void* gsrc) {
    unsigned s = (unsigned)__cvta_generic_to_shared(sdst);
    asm volatile("cp.async.ca.shared.global [%0], [%1], 16;" :: "r"(s), "l"(gsrc));
}
__device__ __forceinline__ void cp_commit() { asm volatile("cp.async.commit_group;"); }
__device__ __forceinline__ void cp_wait0()  { asm volatile("cp.async.wait_group 0;" ::: "memory"); }

// Extract h/r/t columns + relation histogram. Dtype detected inline:
// int64 triples (indices < 500) have all-zero odd 32-bit words.
__global__ void prep_kernel(const int* __restrict__ pos, const int* __restrict__ neg) {
    int i = blockIdx.x * blockDim.x + threadIdx.x;
    if (i >= NITEMS) return;
    const int sh = ((pos[1] | pos[3] | pos[5] | pos[7] |
                     pos[9] | pos[11] | pos[13] | pos[15]) == 0) ? 1 : 0;
    const int* q = (i < BATCH) ? pos : neg;
    const int  j = (i < BATCH) ? i : i - BATCH;
    int rr = q[(3 * j + 1) << sh];
    g_h[i] = q[(3 * j + 0) << sh];
    g_r[i] = rr;
    g_t[i] = q[(3 * j + 2) << sh];
    atomicAdd(&g_cnt[rr], 1);
}

// Prefix-scan counts -> offsets; also build the slab worklist.
__global__ void scan_kernel() {      // 512 threads
    __shared__ int ws[16], ws2[16];
    const int tid = threadIdx.x, lane = tid & 31, w = tid >> 5;
    const int x  = (tid < RELS) ? g_cnt[tid] : 0;          // items for relation tid
    const int y  = (2 * x + 63) >> 6;                       // slabs for relation tid

    int v = x, u = y;
    #pragma unroll
    for (int o = 1; o < 32; o <<= 1) {
        int a = __shfl_up_sync(0xffffffffu, v, o);
        int b = __shfl_up_sync(0xffffffffu, u, o);
        if (lane >= o) { v += a; u += b; }
    }
    if (lane == 31) { ws[w] = v; ws2[w] = u; }
    __syncthreads();
    if (w == 0) {
        int s  = (lane < 16) ? ws[lane]  : 0;
        int s2 = (lane < 16) ? ws2[lane] : 0;
        #pragma unroll
        for (int o = 1; o < 16; o <<= 1) {
            int a = __shfl_up_sync(0xffffffffu, s,  o);
            int b = __shfl_up_sync(0xffffffffu, s2, o);
            if (lane >= o) { s += a; s2 += b; }
        }
        if (lane < 16) { ws[lane] = s; ws2[lane] = s2; }
    }
    __syncthreads();
    const int inc  = v + ((w > 0) ? ws[w - 1]  : 0);
    const int incs = u + ((w > 0) ? ws2[w - 1] : 0);
    if (tid < RELS) {
        g_off[tid + 1] = inc;
        g_cur[tid]     = inc - x;
        int sb = incs - y;
        for (int s = 0; s < y; s++)
            g_slab[sb + s] = (tid << 9) | s;
    }
    if (tid == 0)   g_off[0] = 0;
    if (tid == 511) g_nslabs = incs;
}

__global__ void scatter_kernel() {
    int i = blockIdx.x * blockDim.x + threadIdx.x;
    if (i >= NITEMS) return;
    int p = atomicAdd(&g_cur[g_r[i]], 1);
    g_bucket[p] = i;
}

// R6/R8 mainloop (measured 57% fma): float4 V + pack MOVs, LDS.64 M operands.
// MASKED=false is the dense path; masked variant only for tail slabs.
template<bool MASKED>
__device__ __forceinline__ void mainloop(
    const float* __restrict__ Mr, const float* __restrict__ ent,
    const int* s_eid,
    float (*Mt)[KB][DIM], float (*Vp)[KB][68],
    ull acc[8][4], int tid, int tx, int ty, bool active)
{
    float4 vr[2];

    // ---- prologue: stage panel 0 into buffer 0 ----
    {
        #pragma unroll
        for (int j = 0; j < 4; j++) {
            int idx = tid + 128 * j, row = idx >> 5, c4 = idx & 31;
            cp_async16(&Mt[0][row][c4 * 4], &Mr[row * DIM + c4 * 4]);
        }
        cp_commit();
        #pragma unroll
        for (int j = 0; j < 2; j++) {
            int idx = tid + 128 * j, v = idx >> 2, q = idx & 3;
            vr[j] = *(const float4*)&ent[(long long)s_eid[v] * DIM + q * 4];
        }
        cp_wait0();
        #pragma unroll
        for (int j = 0; j < 2; j++) {
            int idx = tid + 128 * j, v = idx >> 2, q = idx & 3;
            Vp[0][q * 4 + 0][v] = vr[j].x;
            Vp[0][q * 4 + 1][v] = vr[j].y;
            Vp[0][q * 4 + 2][v] = vr[j].z;
            Vp[0][q * 4 + 3][v] = vr[j].w;
        }
        __syncthreads();
    }

    #pragma unroll 1
    for (int kbi = 0; kbi < 8; kbi++) {
        const int cur = kbi & 1, nxt = cur ^ 1;
        const int kb2 = (kbi + 1) * KB;

        // issue next panel's loads before computing current
        if (kbi < 7) {
            #pragma unroll
            for (int j = 0; j < 4; j++) {
                int idx = tid + 128 * j, row = idx >> 5, c4 = idx & 31;
                cp_async16(&Mt[nxt][row][c4 * 4], &Mr[(kb2 + row) * DIM + c4 * 4]);
            }
            cp_commit();
            #pragma unroll
            for (int j = 0; j < 2; j++) {
                int idx = tid + 128 * j, v = idx >> 2, q = idx & 3;
                vr[j] = *(const float4*)&ent[(long long)s_eid[v] * DIM + kb2 + q * 4];
            }
        }

        // ---- compute on current buffer ----
        if (!MASKED || active) {
            #pragma unroll
            for (int k = 0; k < KB; k++) {
                const ull* mrow = (const ull*)&Mt[cur][k][0];
                const ull mp0 = mrow[2 * tx];
                const ull mp1 = mrow[2 * tx + 1];
                const ull mp2 = mrow[32 + 2 * tx];
                const ull mp3 = mrow[32 + 2 * tx + 1];
                const float4 va = *(const float4*)&Vp[cur][k][8 * ty];
                const float4 vb = *(const float4*)&Vp[cur][k][8 * ty + 4];
                const float vs[8] = {va.x, va.y, va.z, va.w, vb.x, vb.y, vb.z, vb.w};
                #pragma unroll
                for (int i = 0; i < 8; i++) {
                    ull vv = pack2(vs[i], vs[i]);
                    ffma2(acc[i][0], mp0, vv);
                    ffma2(acc[i][1], mp1, vv);
                    ffma2(acc[i][2], mp2, vv);
                    ffma2(acc[i][3], mp3, vv);
                }
            }
        }

        if (kbi < 7) {
            cp_wait0();
            #pragma unroll
            for (int j = 0; j < 2; j++) {
                int idx = tid + 128 * j, v = idx >> 2, q = idx & 3;
                Vp[nxt][q * 4 + 0][v] = vr[j].x;
                Vp[nxt][q * 4 + 1][v] = vr[j].y;
                Vp[nxt][q * 4 + 2][v] = vr[j].z;
                Vp[nxt][q * 4 + 3][v] = vr[j].w;
            }
        }
        __syncthreads();
    }
}

__global__ void __launch_bounds__(128, 4) score_kernel(
    const float* __restrict__ ent,
    const float* __restrict__ rel,
    const float* __restrict__ tm)
{
    const int b = blockIdx.x;
    if (b >= g_nslabs) return;
    const int packed = g_slab[b];
    const int r    = packed >> 9;
    const int slab = (packed & 511) << 6;    // first vector index of this slab

    const int tid = threadIdx.x;
    const int tx  = tid & 15;      // col group (8 cols: 4tx.. and 64+4tx..)
    const int ty  = tid >> 4;      // vec group (vectors 8ty..8ty+7)
    const int w   = tid >> 5;      // warp: owns vectors 16w..16w+15 of the slab

    __shared__ __align__(16) float Mt[2][KB][DIM];   // double-buffered M k-panels
    __shared__ __align__(16) float Vp[2][KB][68];    // double-buffered V k-panels
    __shared__ float rnorm[DIM];
    __shared__ float sbuf[4];
    __shared__ int   s_eid[64];

    const int beg = g_off[r];
    const int n   = g_off[r + 1] - beg;
    const int nv  = 2 * n;
    const int m_slab = min(64, nv - slab);           // live vectors in this slab
    const bool active = (16 * w < m_slab);           // uniform per warp
    const float* Mr = tm + (long long)r * (DIM * DIM);

    // Normalized relation vector
    {
        float v = rel[r * DIM + tid];
        float ss = v * v;
        #pragma unroll
        for (int o = 16; o > 0; o >>= 1) ss += __shfl_xor_sync(0xffffffffu, ss, o);
        if ((tid & 31) == 0) sbuf[tid >> 5] = ss;
        __syncthreads();
        float tot = sbuf[0] + sbuf[1] + sbuf[2] + sbuf[3];
        rnorm[tid] = v / fmaxf(sqrtf(tot), 1e-12f);
    }

    // Gather entity ids for this slab's 64 vectors (h,t interleaved)
    if (tid < 64) {
        int vec = slab + tid;
        int e = 0;
        if (vec < nv) {
            int id = g_bucket[beg + (vec >> 1)];
            e = (vec & 1) ? g_t[id] : g_h[id];
        }
        s_eid[tid] = e;
    }
    __syncthreads();

    float4 ra = *(const float4*)&rnorm[4 * tx];
    float4 rb = *(const float4*)&rnorm[64 + 4 * tx];

    ull acc[8][4];
    #pragma unroll
    for (int i = 0; i < 8; i++)
        #pragma unroll
        for (int j = 0; j < 4; j++) acc[i][j] = 0ull;

    if (m_slab == 64)
        mainloop<false>(Mr, ent, s_eid, Mt, Vp, acc, tid, tx, ty, true);
    else
        mainloop<true>(Mr, ent, s_eid, Mt, Vp, acc, tid, tx, ty, active);

    if (!active) return;

    // ---- barrier-free epilogue: 16-lane (half-warp) shuffle reductions ----
    float invv[8];
    #pragma unroll
    for (int i = 0; i < 8; i++) {
        float a, b2, c, d, e, f, g, h;
        unpack2(acc[i][0], a, b2);
        unpack2(acc[i][1], c, d);
        unpack2(acc[i][2], e, f);
        unpack2(acc[i][3], g, h);
        float ss = a * a + b2 * b2 + c * c + d * d + e * e + f * f + g * g + h * h;
        #pragma unroll
        for (int o = 1; o < 16; o <<= 1)
            ss += __shfl_xor_sync(0xffffffffu, ss, o);
        invv[i] = 1.0f / fmaxf(sqrtf(ss), 1e-12f);
    }

    #pragma unroll
    for (int p = 0; p < 4; p++) {
        float h0, h1, h2, h3, h4, h5, h6, h7;
        float t0, t1, t2, t3, t4, t5, t6, t7;
        unpack2(acc[2 * p][0], h0, h1);
        unpack2(acc[2 * p][1], h2, h3);
        unpack2(acc[2 * p][2], h4, h5);
        unpack2(acc[2 * p][3], h6, h7);
        unpack2(acc[2 * p + 1][0], t0, t1);
        unpack2(acc[2 * p + 1][1], t2, t3);
        unpack2(acc[2 * p + 1][2], t4, t5);
        unpack2(acc[2 * p + 1][3], t6, t7);
        const float ih = invv[2 * p];
        const float it = invv[2 * p + 1];
        float sc = fabsf(h0 * ih + ra.x - t0 * it)
                 + fabsf(h1 * ih + ra.y - t1 * it)
                 + fabsf(h2 * ih + ra.z - t2 * it)
                 + fabsf(h3 * ih + ra.w - t3 * it)
                 + fabsf(h4 * ih + rb.x - t4 * it)
                 + fabsf(h5 * ih + rb.y - t5 * it)
                 + fabsf(h6 * ih + rb.z - t6 * it)
                 + fabsf(h7 * ih + rb.w - t7 * it);
        #pragma unroll
        for (int o = 1; o < 16; o <<= 1)
            sc += __shfl_xor_sync(0xffffffffu, sc, o);
        if (tx == 0) {
            int item_local = (slab >> 1) + 4 * ty + p;
            if (item_local < n)
                g_s[g_bucket[beg + item_local]] = sc;
        }
    }
}

__global__ void reduce_kernel(float* __restrict__ out) {   // 1024 threads
    __shared__ float sbuf[32];
    const int tid = threadIdx.x;
    float v = 0.f;
    #pragma unroll
    for (int it = 0; it < 2; it++) {
        int i = tid + 1024 * it;
        float4 p = *(const float4*)&g_s[4 * i];
        float4 q = *(const float4*)&g_s[4 * i + BATCH];
        v += fmaxf(p.x - q.x + 1.0f, 0.0f);
        v += fmaxf(p.y - q.y + 1.0f, 0.0f);
        v += fmaxf(p.z - q.z + 1.0f, 0.0f);
        v += fmaxf(p.w - q.w + 1.0f, 0.0f);
    }
    #pragma unroll
    for (int o = 16; o > 0; o >>= 1)
        v += __shfl_xor_sync(0xffffffffu, v, o);
    if ((tid & 31) == 0) sbuf[tid >> 5] = v;
    // re-zero histogram for the next graph replay (invariant: zero on entry)
    if (tid < 512) g_cnt[tid] = 0;
    __syncthreads();
    if (tid == 0) {
        float s = 0.f;
        #pragma unroll
        for (int i = 0; i < 32; i++) s += sbuf[i];
        out[0] = s * (1.0f / (float)BATCH);
    }
}

extern "C" void kernel_launch(void* const* d_in, const int* in_sizes, int n_in,
                              void* d_out, int out_size) {
    const void*  pos = d_in[0];
    const void*  neg = d_in[1];
    const float* ent = (const float*)d_in[2];
    const float* rel = (const float*)d_in[3];
    const float* tm  = (const float*)d_in[4];

    prep_kernel<<<(NITEMS + 255) / 256, 256>>>((const int*)pos, (const int*)neg);
    scan_kernel<<<1, 512>>>();
    scatter_kernel<<<(NITEMS + 255) / 256, 256>>>();
    score_kernel<<<MAXSLABS, 128>>>(ent, rel, tm);
    reduce_kernel<<<1, 1024>>>((float*)d_out);
}